// round 9
// baseline (speedup 1.0000x reference)
#include <cuda_runtime.h>
#include <math.h>
#define G 128
#define NT 256
#define TT 4800
typedef unsigned long long u64;
typedef unsigned int u32;

// SMEM float offsets
#define OFF_G1I 0
#define OFF_G1H 6144
#define OFF_G2I 12288
#define OFF_G2H 18816
#define OFF_F1W 24960
#define OFF_F2W 27136
#define OFF_F3W 29312
#define OFF_W0  31360
#define OFF_G1B 31872
#define OFF_G2B 31888
#define OFF_F1B 31904
#define OFF_F2B 31908
#define OFF_F3B 31912
#define OFF_ACTA 31916
#define OFF_ACTH 34092
#define OFF_ACTH2 36140
#define OFF_AUX 38188
#define OFF_STAG 38572
#define OFF_SH1 38668
#define OFF_SH2 38716
#define OFF_SAMP 38764
#define SMEMF 38768
#define SMEM_BYTES (SMEMF*4)

__device__ float g_x2[2048], g_x3[2048], g_y1[2048], g_y2[2048];
__device__ float g_h1[2][2048], g_h2[2][2048];
__device__ u64 g_cand[G*4];
__device__ float g_pre[(size_t)TT*2048];
__device__ u32 g_fl[G*32];   // one 128B line per CTA; monotonic across replays

__device__ __forceinline__ u32 ld_acq(const u32* p){
    u32 v; asm volatile("ld.acquire.gpu.global.b32 %0,[%1];":"=r"(v):"l"(p):"memory"); return v;
}
__device__ __forceinline__ void st_rel(u32* p, u32 v){
    asm volatile("st.release.gpu.global.b32 [%0],%1;"::"l"(p),"r"(v):"memory");
}
__device__ __forceinline__ u64 pk2(float x){ u64 r; asm("mov.b64 %0,{%1,%1};":"=l"(r):"f"(x)); return r; }
__device__ __forceinline__ void fma2(u64& d,u64 a,u64 b){ asm("fma.rn.f32x2 %0,%1,%2,%0;":"+l"(d):"l"(a),"l"(b)); }
__device__ __forceinline__ u64 add2(u64 a,u64 b){ u64 r; asm("add.rn.f32x2 %0,%1,%2;":"=l"(r):"l"(a),"l"(b)); return r; }
__device__ __forceinline__ void unpk(u64 v,float& lo,float& hi){ asm("mov.b64 {%0,%1},%2;":"=f"(lo),"=f"(hi):"l"(v)); }
__device__ __forceinline__ void lds2(u64& a,u64& b,u32 addr){
    asm volatile("ld.shared.v2.u64 {%0,%1},[%2];":"=l"(a),"=l"(b):"r"(addr));
}

// proven flag-array grid barrier: per-CTA epoch base, monotonic across replays
#define BAR() do{ ep++; __syncthreads(); \
    if(tid==0) st_rel(&g_fl[bx*32],ep); \
    if(tid<G){ const u32* f=&g_fl[tid*32]; while((int)(ld_acq(f)-ep)<0){} } \
    __syncthreads(); }while(0)

__device__ __forceinline__ void ldx(float* dst,const float* src){
    float4* D=(float4*)dst; const float4* S=(const float4*)src;
    for(int i=threadIdx.x;i<512;i+=NT) D[i]=__ldcg(S+i);
}

// 8-warp 3-gate GEMV: warp w handles neuron w>>1, K-half w&1. Staging: (n*2+kh)*12+g*4+b.
__device__ __forceinline__ void gemv3(float* sm,u32 smb,int offW,int K,float* SD){
    const int tid=threadIdx.x,w=tid>>5,lane=tid&31,n=w>>1,kh=w&1;
    const int Kh=(K+1)>>1;
    const u32 aB=smb+(u32)OFF_ACTA*4u;
    const float* W0=sm+offW+n*3*K;
    const float* W1=W0+K; const float* W2=W1+K;
    u64 ac[6]={0,0,0,0,0,0};
    const int kb=kh*Kh, ke=(kb+Kh<K)?(kb+Kh):K;
    #pragma unroll 2
    for(int k=kb+lane;k<ke;k+=32){
        u64 a01,a23; lds2(a01,a23,aB+(u32)k*16u);
        u64 w0=pk2(W0[k]),w1=pk2(W1[k]),w2=pk2(W2[k]);
        fma2(ac[0],w0,a01); fma2(ac[1],w0,a23);
        fma2(ac[2],w1,a01); fma2(ac[3],w1,a23);
        fma2(ac[4],w2,a01); fma2(ac[5],w2,a23);
    }
    #pragma unroll
    for(int o=16;o;o>>=1)
        #pragma unroll
        for(int j=0;j<6;j++) ac[j]=add2(ac[j],__shfl_xor_sync(~0u,ac[j],o));
    if(!lane){
        float* S=SD+(n*2+kh)*12;
        unpk(ac[0],S[0],S[1]); unpk(ac[1],S[2],S[3]);
        unpk(ac[2],S[4],S[5]); unpk(ac[3],S[6],S[7]);
        unpk(ac[4],S[8],S[9]); unpk(ac[5],S[10],S[11]);
    }
}

// 4-warp (warps 4-7) hidden-side 3-gate GEMV, full K=512 per warp. Staging: n*12+g*4+b.
__device__ __forceinline__ void gemvh(float* sm,u32 smb,int offW,int offA,float* SD){
    const int tid=threadIdx.x,n=(tid>>5)-4,lane=tid&31;
    const u32 aB=smb+(u32)offA*4u;
    const float* W0=sm+offW+n*1536;
    const float* W1=W0+512; const float* W2=W1+512;
    u64 ac[6]={0,0,0,0,0,0};
    #pragma unroll 2
    for(int k=lane;k<512;k+=32){
        u64 a01,a23; lds2(a01,a23,aB+(u32)k*16u);
        u64 w0=pk2(W0[k]),w1=pk2(W1[k]),w2=pk2(W2[k]);
        fma2(ac[0],w0,a01); fma2(ac[1],w0,a23);
        fma2(ac[2],w1,a01); fma2(ac[3],w1,a23);
        fma2(ac[4],w2,a01); fma2(ac[5],w2,a23);
    }
    #pragma unroll
    for(int o=16;o;o>>=1)
        #pragma unroll
        for(int j=0;j<6;j++) ac[j]=add2(ac[j],__shfl_xor_sync(~0u,ac[j],o));
    if(!lane){
        float* S=SD+n*12;
        unpk(ac[0],S[0],S[1]); unpk(ac[1],S[2],S[3]);
        unpk(ac[2],S[4],S[5]); unpk(ac[3],S[6],S[7]);
        unpk(ac[4],S[8],S[9]); unpk(ac[5],S[10],S[11]);
    }
}

// gate combine: SI has 2 K-half partials, SH single; writes x-out and h-out to global
__device__ __forceinline__ void gru_combine(float* sm,int offB,int offHH,const float* SH,
                                            int n0,float* xo,float* ho){
    const int tid=threadIdx.x;
    if(tid<16){
        int nn=tid>>2,b=tid&3;
        const float* S0=sm+OFF_STAG+(nn*2)*12;
        const float* S1=S0+12;
        const float* H=SH+nn*12;
        const float* B=sm+offB+nn*4;
        float ir=S0[b]+S1[b],       iz=S0[4+b]+S1[4+b],   in_=S0[8+b]+S1[8+b];
        float r=1.f/(1.f+expf(-(ir+H[b]+B[0])));
        float z=1.f/(1.f+expf(-(iz+H[4+b]+B[1])));
        float nv=tanhf(in_+B[2]+r*(H[8+b]+B[3]));
        float hv=(1.f-z)*nv+z*sm[offHH+(n0+nn)*4+b];
        ho[(n0+nn)*4+b]=hv;
        xo[(n0+nn)*4+b]=sm[OFF_ACTA+(n0+nn)*4+b]+hv;
    }
}

__device__ __forceinline__ void fc_stage(float* sm,u32 smb,int offW,int offB,int K,int n0,
                                         float* dd,bool relu){
    const int tid=threadIdx.x,w=tid>>5,lane=tid&31,n=w>>1,kh=w&1,Kh=K>>1;
    const u32 aB=smb+(u32)OFF_ACTA*4u;
    const float* W=sm+offW+n*K;
    u64 a01=0,a23=0;
    #pragma unroll 2
    for(int k=kh*Kh+lane;k<kh*Kh+Kh;k+=32){
        u64 x01,x23; lds2(x01,x23,aB+(u32)k*16u);
        u64 ww=pk2(W[k]);
        fma2(a01,ww,x01); fma2(a23,ww,x23);
    }
    #pragma unroll
    for(int o=16;o;o>>=1){ a01=add2(a01,__shfl_xor_sync(~0u,a01,o)); a23=add2(a23,__shfl_xor_sync(~0u,a23,o)); }
    if(!lane){ float* S=sm+OFF_STAG+w*4; unpk(a01,S[0],S[1]); unpk(a23,S[2],S[3]); }
    __syncthreads();
    if(tid<16){
        int nn=tid>>2,b=tid&3;
        float v=sm[OFF_STAG+nn*8+b]+sm[OFF_STAG+nn*8+4+b]+sm[offB+nn];
        if(relu)v=fmaxf(v,0.f);
        dd[(n0+nn)*4+b]=v;
    }
}

extern "C" __global__ void __launch_bounds__(NT,1) wavernn_kernel(
    const float* __restrict__ mel,   const float* __restrict__ aux,
    const float* __restrict__ WI,    const float* __restrict__ bI,
    const float* __restrict__ g1wih, const float* __restrict__ g1whh,
    const float* __restrict__ g1bih, const float* __restrict__ g1bhh,
    const float* __restrict__ g2wih, const float* __restrict__ g2whh,
    const float* __restrict__ g2bih, const float* __restrict__ g2bhh,
    const float* __restrict__ f1w,   const float* __restrict__ f1b,
    const float* __restrict__ f2w,   const float* __restrict__ f2b,
    const float* __restrict__ f3w,   const float* __restrict__ f3b,
    float* __restrict__ out)
{
    extern __shared__ float sm[];
    const int tid=threadIdx.x, bx=blockIdx.x, n0=bx*4;
    const u32 smb=(u32)__cvta_generic_to_shared(sm);
    u32 ep=ld_acq(&g_fl[bx*32]);   // own flag: race-free monotonic base

    // one-time: pre[t] = b_I + W_I[:,1:]*[mel,aux0]
    {
        int t0=bx*TT/G, t1=(bx+1)*TT/G;
        for(int p=0;p<4;p++){
            for(int i=tid;i<128*112;i+=NT){int j=i/112,c=i-j*112;sm[j*112+c]=__ldg(&WI[(p*128+j)*113+1+c]);}
            __syncthreads();
            int jl=tid>>1,bh=tid&1,j=p*128+jl;
            float bias=__ldg(&bI[j]);
            const float* Wr=sm+jl*112;
            for(int t=t0;t<t1;t++){
                float a0=bias,a1=bias;
                const float*m0=mel+((size_t)(bh*2)*TT+t)*80,*m1=mel+((size_t)(bh*2+1)*TT+t)*80;
                const float*x0=aux+((size_t)(bh*2)*TT+t)*128,*x1=aux+((size_t)(bh*2+1)*TT+t)*128;
                #pragma unroll 8
                for(int c=0;c<80;c++){float wv=Wr[c];a0=fmaf(wv,__ldg(m0+c),a0);a1=fmaf(wv,__ldg(m1+c),a1);}
                #pragma unroll 8
                for(int c=0;c<32;c++){float wv=Wr[80+c];a0=fmaf(wv,__ldg(x0+c),a0);a1=fmaf(wv,__ldg(x1+c),a1);}
                g_pre[((size_t)t*512+j)*4+bh*2]=a0; g_pre[((size_t)t*512+j)*4+bh*2+1]=a1;
            }
            __syncthreads();
        }
    }
    // weights into SMEM
    for(int i=tid;i<6144;i+=NT){int j=i/1536,r=i-j*1536,g=r>>9,k=r&511;
        sm[OFF_G1I+i]=__ldg(&g1wih[(g*512+n0+j)*512+k]);
        sm[OFF_G1H+i]=__ldg(&g1whh[(g*512+n0+j)*512+k]);
        sm[OFF_G2H+i]=__ldg(&g2whh[(g*512+n0+j)*512+k]);}
    for(int i=tid;i<6528;i+=NT){int j=i/1632,r=i-j*1632,g=r/544,k=r-g*544;
        sm[OFF_G2I+i]=__ldg(&g2wih[(g*512+n0+j)*544+k]);}
    for(int i=tid;i<2176;i+=NT){int j=i/544,k=i-j*544;
        sm[OFF_F1W+i]=__ldg(&f1w[(n0+j)*544+k]); sm[OFF_F2W+i]=__ldg(&f2w[(n0+j)*544+k]);}
    for(int i=tid;i<2048;i+=NT) sm[OFF_F3W+i]=__ldg(&f3w[(n0+(i>>9))*512+(i&511)]);
    for(int i=tid;i<512;i+=NT)  sm[OFF_W0+i]=__ldg(&WI[i*113]);
    if(tid<16){
        int nn=tid>>2,c=tid&3,n=n0+nn; float v1,v2;
        if(c==0){v1=g1bih[n]+g1bhh[n];v2=g2bih[n]+g2bhh[n];}
        else if(c==1){v1=g1bih[512+n]+g1bhh[512+n];v2=g2bih[512+n]+g2bhh[512+n];}
        else if(c==2){v1=g1bih[1024+n];v2=g2bih[1024+n];}
        else{v1=g1bhh[1024+n];v2=g2bhh[1024+n];}
        sm[OFF_G1B+tid]=v1; sm[OFF_G2B+tid]=v2;
        g_h1[0][(n0+nn)*4+c]=0.f; g_h2[0][(n0+nn)*4+c]=0.f;
    }
    if(tid<4){sm[OFF_F1B+tid]=f1b[n0+tid];sm[OFF_F2B+tid]=f2b[n0+tid];sm[OFF_F3B+tid]=f3b[n0+tid];sm[OFF_SAMP+tid]=0.f;}
    BAR();

    float* outL=out+4*TT;
    for(int t=0;t<TT;t++){
        const int p=t&1;
        // ---- step top: two concurrent warp groups ----
        if(tid<128){
            // warps 0-3: pre (in flight) + aux + argmax + sample + build x
            float4 pv0,pv1,pv2,pv3;
            const float4* gp=(const float4*)g_pre+((size_t)t*512+tid*4);
            pv0=__ldcg(gp); pv1=__ldcg(gp+1); pv2=__ldcg(gp+2); pv3=__ldcg(gp+3);
            if(tid<96){int seg=tid>>5,c=tid&31,col=(seg+1)*32+c;
                ((float4*)(sm+OFF_AUX))[seg*32+c]=make_float4(
                    aux[((size_t)0*TT+t)*128+col],aux[((size_t)1*TT+t)*128+col],
                    aux[((size_t)2*TT+t)*128+col],aux[((size_t)3*TT+t)*128+col]);}
            int w=tid>>5, lane=tid&31;
            if(t){
                u64 c=0ull;
                #pragma unroll
                for(int j=0;j<4;j++){ u64 v=__ldcg(&g_cand[(lane+32*j)*4+w]); if(v>c)c=v; }
                #pragma unroll
                for(int o=16;o;o>>=1){ u64 v=__shfl_xor_sync(~0u,c,o); if(v>c)c=v; }
                if(lane==0){
                    int idx=511-(int)(c&0xffffffffull);
                    float s=2.f*(float)idx/511.f-1.f;
                    sm[OFF_SAMP+w]=s;
                    if(bx==0) out[w*TT+(t-1)]=s;
                }
            }
            asm volatile("bar.sync 1,128;":::"memory");
            float4 sv=*(const float4*)(sm+OFF_SAMP);
            float4* Aa=(float4*)(sm+OFF_ACTA);
            {
                float wv=sm[OFF_W0+tid*4+0]; float4 x;
                x.x=fmaf(wv,sv.x,pv0.x);x.y=fmaf(wv,sv.y,pv0.y);x.z=fmaf(wv,sv.z,pv0.z);x.w=fmaf(wv,sv.w,pv0.w);
                Aa[tid*4+0]=x;
                wv=sm[OFF_W0+tid*4+1];
                x.x=fmaf(wv,sv.x,pv1.x);x.y=fmaf(wv,sv.y,pv1.y);x.z=fmaf(wv,sv.z,pv1.z);x.w=fmaf(wv,sv.w,pv1.w);
                Aa[tid*4+1]=x;
                wv=sm[OFF_W0+tid*4+2];
                x.x=fmaf(wv,sv.x,pv2.x);x.y=fmaf(wv,sv.y,pv2.y);x.z=fmaf(wv,sv.z,pv2.z);x.w=fmaf(wv,sv.w,pv2.w);
                Aa[tid*4+2]=x;
                wv=sm[OFF_W0+tid*4+3];
                x.x=fmaf(wv,sv.x,pv3.x);x.y=fmaf(wv,sv.y,pv3.y);x.z=fmaf(wv,sv.z,pv3.z);x.w=fmaf(wv,sv.w,pv3.w);
                Aa[tid*4+3]=x;
            }
        } else {
            // warps 4-7: prefetch h1,h2; hidden-side GEMVs for both GRUs (off critical path)
            int r=tid-128;
            float4* H1=(float4*)(sm+OFF_ACTH); float4* H2=(float4*)(sm+OFF_ACTH2);
            const float4* s1=(const float4*)g_h1[p]+r*4;
            const float4* s2=(const float4*)g_h2[p]+r*4;
            H1[r*4+0]=__ldcg(s1+0); H1[r*4+1]=__ldcg(s1+1); H1[r*4+2]=__ldcg(s1+2); H1[r*4+3]=__ldcg(s1+3);
            H2[r*4+0]=__ldcg(s2+0); H2[r*4+1]=__ldcg(s2+1); H2[r*4+2]=__ldcg(s2+2); H2[r*4+3]=__ldcg(s2+3);
            asm volatile("bar.sync 2,128;":::"memory");
            gemvh(sm,smb,OFF_G1H,OFF_ACTH, sm+OFF_SH1);
            gemvh(sm,smb,OFF_G2H,OFF_ACTH2,sm+OFF_SH2);
        }
        __syncthreads();
        // P1: GRU1 input-side (all 8 warps) + combine
        gemv3(sm,smb,OFF_G1I,512,sm+OFF_STAG);
        __syncthreads();
        gru_combine(sm,OFF_G1B,OFF_ACTH, sm+OFF_SH1,n0,g_x2,g_h1[p^1]);
        BAR();
        // P2: GRU2 input-side + combine
        ldx(sm+OFF_ACTA,g_x2);
        if(tid<32) ((float4*)(sm+OFF_ACTA))[512+tid]=((const float4*)(sm+OFF_AUX))[tid];
        __syncthreads();
        gemv3(sm,smb,OFF_G2I,544,sm+OFF_STAG);
        __syncthreads();
        gru_combine(sm,OFF_G2B,OFF_ACTH2,sm+OFF_SH2,n0,g_x3,g_h2[p^1]);
        BAR();
        // P3: fc1
        ldx(sm+OFF_ACTA,g_x3);
        if(tid<32) ((float4*)(sm+OFF_ACTA))[512+tid]=((const float4*)(sm+OFF_AUX))[32+tid];
        __syncthreads();
        fc_stage(sm,smb,OFF_F1W,OFF_F1B,544,n0,g_y1,true);
        BAR();
        // P4: fc2
        ldx(sm+OFF_ACTA,g_y1);
        if(tid<32) ((float4*)(sm+OFF_ACTA))[512+tid]=((const float4*)(sm+OFF_AUX))[64+tid];
        __syncthreads();
        fc_stage(sm,smb,OFF_F2W,OFF_F2B,544,n0,g_y2,true);
        BAR();
        // P5: fc3 + argmax keys
        ldx(sm+OFF_ACTA,g_y2);
        __syncthreads();
        {
            const int w=tid>>5,lane=tid&31,n=w>>1,kh=w&1;
            const u32 aB=smb+(u32)OFF_ACTA*4u;
            const float* W=sm+OFF_F3W+n*512;
            u64 a01=0,a23=0;
            #pragma unroll 2
            for(int k=kh*256+lane;k<kh*256+256;k+=32){
                u64 x01,x23; lds2(x01,x23,aB+(u32)k*16u);
                u64 ww=pk2(W[k]);
                fma2(a01,ww,x01); fma2(a23,ww,x23);
            }
            #pragma unroll
            for(int o=16;o;o>>=1){ a01=add2(a01,__shfl_xor_sync(~0u,a01,o)); a23=add2(a23,__shfl_xor_sync(~0u,a23,o)); }
            if(!lane){ float* S=sm+OFF_STAG+w*4; unpk(a01,S[0],S[1]); unpk(a23,S[2],S[3]); }
            __syncthreads();
            if(tid<16){
                int nn=tid>>2,b=tid&3;
                float v=sm[OFF_STAG+nn*8+b]+sm[OFF_STAG+nn*8+4+b]+sm[OFF_F3B+nn];
                outL[((size_t)b*TT+t)*512+n0+nn]=v;
                u32 u=__float_as_uint(v); u=(u&0x80000000u)?~u:(u|0x80000000u);
                u64 key=((u64)u<<32)|(u32)(511-(n0+nn));
                u64 v1=__shfl_xor_sync(0xffffu,key,4); if(v1>key)key=v1;
                u64 v2=__shfl_xor_sync(0xffffu,key,8); if(v2>key)key=v2;
                if(tid<4) g_cand[bx*4+tid]=key;
            }
        }
        BAR();
    }
    // tail: final sample from last step's keys (visible after last BAR)
    if(bx==0 && tid<128){
        int w=tid>>5, lane=tid&31;
        u64 c=0ull;
        #pragma unroll
        for(int j=0;j<4;j++){ u64 v=__ldcg(&g_cand[(lane+32*j)*4+w]); if(v>c)c=v; }
        #pragma unroll
        for(int o=16;o;o>>=1){ u64 v=__shfl_xor_sync(~0u,c,o); if(v>c)c=v; }
        if(lane==0){
            int idx=511-(int)(c&0xffffffffull);
            out[w*TT+TT-1]=2.f*(float)idx/511.f-1.f;
        }
    }
}

extern "C" void kernel_launch(void* const* d_in, const int* in_sizes, int n_in,
                              void* d_out, int out_size){
    (void)in_sizes;(void)n_in;(void)out_size;
    cudaFuncSetAttribute(wavernn_kernel, cudaFuncAttributeMaxDynamicSharedMemorySize, SMEM_BYTES);
    wavernn_kernel<<<G,NT,SMEM_BYTES>>>(
        (const float*)d_in[0],(const float*)d_in[1],(const float*)d_in[2],
        (const float*)d_in[3],(const float*)d_in[4],(const float*)d_in[5],
        (const float*)d_in[6],(const float*)d_in[7],(const float*)d_in[8],
        (const float*)d_in[9],(const float*)d_in[10],(const float*)d_in[11],
        (const float*)d_in[12],(const float*)d_in[13],(const float*)d_in[14],
        (const float*)d_in[15],(const float*)d_in[16],(const float*)d_in[17],
        (float*)d_out);
}

// round 10
// speedup vs baseline: 1.0897x; 1.0897x over previous
#include <cuda_runtime.h>
#include <math.h>
#define G 128
#define NT 512
#define TT 4800
typedef unsigned long long u64;
typedef unsigned int u32;

// SMEM float offsets
#define OFF_G1I 0
#define OFF_G1H 6144
#define OFF_G2I 12288
#define OFF_G2H 18816
#define OFF_F1W 24960
#define OFF_F2W 27136
#define OFF_F3W 29312
#define OFF_W0  31360
#define OFF_G1B 31872
#define OFF_G2B 31888
#define OFF_F1B 31904
#define OFF_F2B 31908
#define OFF_F3B 31912
#define OFF_ACTA 31916
#define OFF_ACTH 34092
#define OFF_ACTH2 36140
#define OFF_AUX 38188
#define OFF_STAG 38572
#define OFF_SAMP 38764
#define SMEMF 38768
#define SMEM_BYTES (SMEMF*4)

__device__ float g_x2[2048], g_x3[2048], g_y1[2048], g_y2[2048];
__device__ float g_h1[2][2048], g_h2[2][2048];
__device__ u64 g_cand[G*4];
__device__ float g_pre[(size_t)TT*2048];
__device__ u32 g_fl[G*32];   // one 128B line per CTA; monotonic across replays

__device__ __forceinline__ u32 ld_acq(const u32* p){
    u32 v; asm volatile("ld.acquire.gpu.global.b32 %0,[%1];":"=r"(v):"l"(p):"memory"); return v;
}
__device__ __forceinline__ void st_rel(u32* p, u32 v){
    asm volatile("st.release.gpu.global.b32 [%0],%1;"::"l"(p),"r"(v):"memory");
}
__device__ __forceinline__ u64 pk2(float x){ u64 r; asm("mov.b64 %0,{%1,%1};":"=l"(r):"f"(x)); return r; }
__device__ __forceinline__ void fma2(u64& d,u64 a,u64 b){ asm("fma.rn.f32x2 %0,%1,%2,%0;":"+l"(d):"l"(a),"l"(b)); }
__device__ __forceinline__ u64 add2(u64 a,u64 b){ u64 r; asm("add.rn.f32x2 %0,%1,%2;":"=l"(r):"l"(a),"l"(b)); return r; }
__device__ __forceinline__ void unpk(u64 v,float& lo,float& hi){ asm("mov.b64 {%0,%1},%2;":"=f"(lo),"=f"(hi):"l"(v)); }
__device__ __forceinline__ void lds2(u64& a,u64& b,u32 addr){
    asm volatile("ld.shared.v2.u64 {%0,%1},[%2];":"=l"(a),"=l"(b):"r"(addr));
}

// proven flag-array grid barrier: per-CTA epoch base, monotonic across replays
#define BAR() do{ ep++; __syncthreads(); \
    if(tid==0) st_rel(&g_fl[bx*32],ep); \
    if(tid<G){ const u32* f=&g_fl[tid*32]; while((int)(ld_acq(f)-ep)<0){} } \
    __syncthreads(); }while(0)

__device__ __forceinline__ void ldx(float* dst,const float* src){
    ((float4*)dst)[threadIdx.x]=__ldcg((const float4*)src+threadIdx.x);
}

// GRU stage, 16 warps: warp w → neuron w>>2, q=w&3: side=q>>1 (0=input,1=hidden), K-half=q&1.
__device__ __forceinline__ void gru_stage(float* sm,u32 smb,int offHH,int offI,int offH,int offB,
                                          int Kin,int n0,float* xo,float* ho){
    const int tid=threadIdx.x,w=tid>>5,lane=tid&31;
    const int n=w>>2,q=w&3,side=q>>1,half=q&1;
    const int K=side?512:Kin, Kh=K>>1;
    const u32 aB=smb+(u32)(side?offHH:OFF_ACTA)*4u;
    const float* W0=side?(sm+offH+n*1536):(sm+offI+n*3*Kin);
    const float* W1=W0+K; const float* W2=W1+K;
    u64 ac[6]={0,0,0,0,0,0};
    const int kb=half*Kh, ke=kb+Kh;
    #pragma unroll 2
    for(int k=kb+lane;k<ke;k+=32){
        u64 a01,a23; lds2(a01,a23,aB+(u32)k*16u);
        u64 w0=pk2(W0[k]),w1=pk2(W1[k]),w2=pk2(W2[k]);
        fma2(ac[0],w0,a01); fma2(ac[1],w0,a23);
        fma2(ac[2],w1,a01); fma2(ac[3],w1,a23);
        fma2(ac[4],w2,a01); fma2(ac[5],w2,a23);
    }
    #pragma unroll
    for(int o=16;o;o>>=1)
        #pragma unroll
        for(int j=0;j<6;j++) ac[j]=add2(ac[j],__shfl_xor_sync(~0u,ac[j],o));
    if(!lane){
        float* S=sm+OFF_STAG+w*12;  // w = n*4 + side*2 + half
        unpk(ac[0],S[0],S[1]); unpk(ac[1],S[2],S[3]);
        unpk(ac[2],S[4],S[5]); unpk(ac[3],S[6],S[7]);
        unpk(ac[4],S[8],S[9]); unpk(ac[5],S[10],S[11]);
    }
    __syncthreads();
    if(tid<16){
        int nn=tid>>2,b=tid&3;
        const float* S=sm+OFF_STAG+nn*48;
        const float* B=sm+offB+nn*4;
        float ir=S[b]+S[12+b],    iz=S[4+b]+S[16+b],  in_=S[8+b]+S[20+b];
        float hr=S[24+b]+S[36+b], hz=S[28+b]+S[40+b], hn =S[32+b]+S[44+b];
        float r=1.f/(1.f+expf(-(ir+hr+B[0])));
        float z=1.f/(1.f+expf(-(iz+hz+B[1])));
        float nv=tanhf(in_+B[2]+r*(hn+B[3]));
        float hv=(1.f-z)*nv+z*sm[offHH+(n0+nn)*4+b];
        ho[(n0+nn)*4+b]=hv;
        xo[(n0+nn)*4+b]=sm[OFF_ACTA+(n0+nn)*4+b]+hv;
    }
}

// FC stage, 16 warps: neuron w>>2, K-quarter w&3.
__device__ __forceinline__ void fc_stage(float* sm,u32 smb,int offW,int offB,int K,int n0,
                                         float* dd,bool relu){
    const int tid=threadIdx.x,w=tid>>5,lane=tid&31,n=w>>2,kq=w&3,Kq=K>>2;
    const u32 aB=smb+(u32)OFF_ACTA*4u;
    const float* W=sm+offW+n*K;
    u64 a01=0,a23=0;
    const int kb=kq*Kq, ke=kb+Kq;
    #pragma unroll 2
    for(int k=kb+lane;k<ke;k+=32){
        u64 x01,x23; lds2(x01,x23,aB+(u32)k*16u);
        u64 ww=pk2(W[k]);
        fma2(a01,ww,x01); fma2(a23,ww,x23);
    }
    #pragma unroll
    for(int o=16;o;o>>=1){ a01=add2(a01,__shfl_xor_sync(~0u,a01,o)); a23=add2(a23,__shfl_xor_sync(~0u,a23,o)); }
    if(!lane){ float* S=sm+OFF_STAG+w*4; unpk(a01,S[0],S[1]); unpk(a23,S[2],S[3]); }
    __syncthreads();
    if(tid<16){
        int nn=tid>>2,b=tid&3;
        const float* S=sm+OFF_STAG+nn*16;
        float v=S[b]+S[4+b]+S[8+b]+S[12+b]+sm[offB+nn];
        if(relu)v=fmaxf(v,0.f);
        dd[(n0+nn)*4+b]=v;
    }
}

extern "C" __global__ void __launch_bounds__(NT,1) wavernn_kernel(
    const float* __restrict__ mel,   const float* __restrict__ aux,
    const float* __restrict__ WI,    const float* __restrict__ bI,
    const float* __restrict__ g1wih, const float* __restrict__ g1whh,
    const float* __restrict__ g1bih, const float* __restrict__ g1bhh,
    const float* __restrict__ g2wih, const float* __restrict__ g2whh,
    const float* __restrict__ g2bih, const float* __restrict__ g2bhh,
    const float* __restrict__ f1w,   const float* __restrict__ f1b,
    const float* __restrict__ f2w,   const float* __restrict__ f2b,
    const float* __restrict__ f3w,   const float* __restrict__ f3b,
    float* __restrict__ out)
{
    extern __shared__ float sm[];
    const int tid=threadIdx.x, bx=blockIdx.x, n0=bx*4;
    const u32 smb=(u32)__cvta_generic_to_shared(sm);
    u32 ep=ld_acq(&g_fl[bx*32]);   // own flag: race-free monotonic base

    // one-time: pre[t] = b_I + W_I[:,1:]*[mel,aux0] ; 512 threads = 128 rows x 4 batches
    {
        int t0=bx*TT/G, t1=(bx+1)*TT/G;
        for(int p=0;p<4;p++){
            for(int i=tid;i<128*112;i+=NT){int j=i/112,c=i-j*112;sm[j*112+c]=__ldg(&WI[(p*128+j)*113+1+c]);}
            __syncthreads();
            int jl=tid>>2, bh=tid&3, j=p*128+jl;
            float bias=__ldg(&bI[j]);
            const float* Wr=sm+jl*112;
            for(int t=t0;t<t1;t++){
                float a=bias;
                const float* m=mel+((size_t)bh*TT+t)*80;
                const float* x=aux+((size_t)bh*TT+t)*128;
                #pragma unroll 8
                for(int c=0;c<80;c++) a=fmaf(Wr[c],__ldg(m+c),a);
                #pragma unroll 8
                for(int c=0;c<32;c++) a=fmaf(Wr[80+c],__ldg(x+c),a);
                g_pre[((size_t)t*512+j)*4+bh]=a;
            }
            __syncthreads();
        }
    }
    // weights into SMEM
    for(int i=tid;i<6144;i+=NT){int j=i/1536,r=i-j*1536,g=r>>9,k=r&511;
        sm[OFF_G1I+i]=__ldg(&g1wih[(g*512+n0+j)*512+k]);
        sm[OFF_G1H+i]=__ldg(&g1whh[(g*512+n0+j)*512+k]);
        sm[OFF_G2H+i]=__ldg(&g2whh[(g*512+n0+j)*512+k]);}
    for(int i=tid;i<6528;i+=NT){int j=i/1632,r=i-j*1632,g=r/544,k=r-g*544;
        sm[OFF_G2I+i]=__ldg(&g2wih[(g*512+n0+j)*544+k]);}
    for(int i=tid;i<2176;i+=NT){int j=i/544,k=i-j*544;
        sm[OFF_F1W+i]=__ldg(&f1w[(n0+j)*544+k]); sm[OFF_F2W+i]=__ldg(&f2w[(n0+j)*544+k]);}
    for(int i=tid;i<2048;i+=NT) sm[OFF_F3W+i]=__ldg(&f3w[(n0+(i>>9))*512+(i&511)]);
    for(int i=tid;i<512;i+=NT)  sm[OFF_W0+i]=__ldg(&WI[i*113]);
    if(tid<16){
        int nn=tid>>2,c=tid&3,n=n0+nn; float v1,v2;
        if(c==0){v1=g1bih[n]+g1bhh[n];v2=g2bih[n]+g2bhh[n];}
        else if(c==1){v1=g1bih[512+n]+g1bhh[512+n];v2=g2bih[512+n]+g2bhh[512+n];}
        else if(c==2){v1=g1bih[1024+n];v2=g2bih[1024+n];}
        else{v1=g1bhh[1024+n];v2=g2bhh[1024+n];}
        sm[OFF_G1B+tid]=v1; sm[OFF_G2B+tid]=v2;
        g_h1[0][(n0+nn)*4+c]=0.f; g_h2[0][(n0+nn)*4+c]=0.f;
    }
    if(tid<4){sm[OFF_F1B+tid]=f1b[n0+tid];sm[OFF_F2B+tid]=f2b[n0+tid];sm[OFF_F3B+tid]=f3b[n0+tid];sm[OFF_SAMP+tid]=0.f;}
    BAR();

    float* outL=out+4*TT;
    for(int t=0;t<TT;t++){
        const int p=t&1;
        // step top: sample known; prefetch pre/h1/h2/aux; build x locally (1 float4/thread)
        float4 sv=*(const float4*)(sm+OFF_SAMP);
        float4 p0=__ldcg((const float4*)g_pre+((size_t)t*512+tid));
        ((float4*)(sm+OFF_ACTH))[tid] =__ldcg((const float4*)g_h1[p]+tid);
        ((float4*)(sm+OFF_ACTH2))[tid]=__ldcg((const float4*)g_h2[p]+tid);
        if(tid<96){int seg=tid>>5,c=tid&31,col=(seg+1)*32+c;
            ((float4*)(sm+OFF_AUX))[seg*32+c]=make_float4(
                aux[((size_t)0*TT+t)*128+col],aux[((size_t)1*TT+t)*128+col],
                aux[((size_t)2*TT+t)*128+col],aux[((size_t)3*TT+t)*128+col]);}
        {
            float wv=sm[OFF_W0+tid]; float4 x;
            x.x=fmaf(wv,sv.x,p0.x);x.y=fmaf(wv,sv.y,p0.y);x.z=fmaf(wv,sv.z,p0.z);x.w=fmaf(wv,sv.w,p0.w);
            ((float4*)(sm+OFF_ACTA))[tid]=x;
        }
        __syncthreads();
        // P1: GRU1
        gru_stage(sm,smb,OFF_ACTH,OFF_G1I,OFF_G1H,OFF_G1B,512,n0,g_x2,g_h1[p^1]);
        BAR();
        // P2: GRU2
        ldx(sm+OFF_ACTA,g_x2);
        if(tid<32) ((float4*)(sm+OFF_ACTA))[512+tid]=((const float4*)(sm+OFF_AUX))[tid];
        __syncthreads();
        gru_stage(sm,smb,OFF_ACTH2,OFF_G2I,OFF_G2H,OFF_G2B,544,n0,g_x3,g_h2[p^1]);
        BAR();
        // P3: fc1
        ldx(sm+OFF_ACTA,g_x3);
        if(tid<32) ((float4*)(sm+OFF_ACTA))[512+tid]=((const float4*)(sm+OFF_AUX))[32+tid];
        __syncthreads();
        fc_stage(sm,smb,OFF_F1W,OFF_F1B,544,n0,g_y1,true);
        BAR();
        // P4: fc2
        ldx(sm+OFF_ACTA,g_y1);
        if(tid<32) ((float4*)(sm+OFF_ACTA))[512+tid]=((const float4*)(sm+OFF_AUX))[64+tid];
        __syncthreads();
        fc_stage(sm,smb,OFF_F2W,OFF_F2B,544,n0,g_y2,true);
        BAR();
        // P5: fc3 + argmax keys (16 warps: neuron w>>2, K-quarter w&3 of 512)
        ldx(sm+OFF_ACTA,g_y2);
        __syncthreads();
        {
            const int w=tid>>5,lane=tid&31,n=w>>2,kq=w&3;
            const u32 aB=smb+(u32)OFF_ACTA*4u;
            const float* W=sm+OFF_F3W+n*512;
            u64 a01=0,a23=0;
            #pragma unroll 2
            for(int k=kq*128+lane;k<kq*128+128;k+=32){
                u64 x01,x23; lds2(x01,x23,aB+(u32)k*16u);
                u64 ww=pk2(W[k]);
                fma2(a01,ww,x01); fma2(a23,ww,x23);
            }
            #pragma unroll
            for(int o=16;o;o>>=1){ a01=add2(a01,__shfl_xor_sync(~0u,a01,o)); a23=add2(a23,__shfl_xor_sync(~0u,a23,o)); }
            if(!lane){ float* S=sm+OFF_STAG+w*4; unpk(a01,S[0],S[1]); unpk(a23,S[2],S[3]); }
            __syncthreads();
            if(tid<16){
                int nn=tid>>2,b=tid&3;
                const float* S=sm+OFF_STAG+nn*16;
                float v=S[b]+S[4+b]+S[8+b]+S[12+b]+sm[OFF_F3B+nn];
                outL[((size_t)b*TT+t)*512+n0+nn]=v;
                u32 u=__float_as_uint(v); u=(u&0x80000000u)?~u:(u|0x80000000u);
                u64 key=((u64)u<<32)|(u32)(511-(n0+nn));
                u64 v1=__shfl_xor_sync(0xffffu,key,4); if(v1>key)key=v1;
                u64 v2=__shfl_xor_sync(0xffffu,key,8); if(v2>key)key=v2;
                if(tid<4) g_cand[bx*4+tid]=key;
            }
        }
        BAR();
        // argmax all-reduce: warp w = batch w
        if(tid<128){
            int w=tid>>5,lane=tid&31;
            u64 c=0ull;
            #pragma unroll
            for(int j=0;j<4;j++){ u64 v=__ldcg(&g_cand[(lane+32*j)*4+w]); if(v>c)c=v; }
            #pragma unroll
            for(int o=16;o;o>>=1){ u64 v=__shfl_xor_sync(~0u,c,o); if(v>c)c=v; }
            if(lane==0){
                int idx=511-(int)(c&0xffffffffull);
                float s=2.f*(float)idx/511.f-1.f;
                sm[OFF_SAMP+w]=s;
                if(bx==0) out[w*TT+t]=s;
            }
        }
        __syncthreads();
    }
}

extern "C" void kernel_launch(void* const* d_in, const int* in_sizes, int n_in,
                              void* d_out, int out_size){
    (void)in_sizes;(void)n_in;(void)out_size;
    cudaFuncSetAttribute(wavernn_kernel, cudaFuncAttributeMaxDynamicSharedMemorySize, SMEM_BYTES);
    wavernn_kernel<<<G,NT,SMEM_BYTES>>>(
        (const float*)d_in[0],(const float*)d_in[1],(const float*)d_in[2],
        (const float*)d_in[3],(const float*)d_in[4],(const float*)d_in[5],
        (const float*)d_in[6],(const float*)d_in[7],(const float*)d_in[8],
        (const float*)d_in[9],(const float*)d_in[10],(const float*)d_in[11],
        (const float*)d_in[12],(const float*)d_in[13],(const float*)d_in[14],
        (const float*)d_in[15],(const float*)d_in[16],(const float*)d_in[17],
        (float*)d_out);
}